// round 1
// baseline (speedup 1.0000x reference)
#include <cuda_runtime.h>
#include <cuda_bf16.h>
#include <math.h>

#define Dm 512
#define DD (512*512)

// ---------------- scratch (device globals; no allocation) ----------------
__device__ __align__(16) float g_seg0[4*1024*512];
__device__ __align__(16) float g_seg1[4*256*512];
__device__ __align__(16) float g_seg2[4*64*512];
__device__ __align__(16) float g_ln  [4*1024*512];
__device__ __align__(16) float g_h   [4096*1024];
__device__ __align__(16) float g_q   [4*1024*512];
__device__ __align__(16) float g_k   [4*1024*512];
__device__ __align__(16) float g_v   [4*1024*512];
__device__ __align__(16) float g_ao  [4*1024*512];
__device__ __align__(16) float g_sc  [4*4*1024*256];
__device__ int g_starts[4*1025 + 4*257 + 4*65];

// ---------------- boundary scan: starts[s] = index of s-th boundary ------
__global__ void starts_kernel(const int* __restrict__ b, int* __restrict__ starts,
                              int L, int nseg) {
    int batch = blockIdx.x;
    int lane = threadIdx.x;          // 32 threads
    const int* bi = b + (long)batch * L;
    int* st = starts + (long)batch * (nseg + 1);
    // init all (covers missing boundaries -> empty segments)
    for (int s = lane; s <= nseg; s += 32) st[s] = L;
    __syncwarp();
    int base = 0;
    for (int i0 = 0; i0 < L; i0 += 32) {
        int i = i0 + lane;
        int v = (i < L) ? bi[i] : 0;
        unsigned m = __ballot_sync(0xffffffffu, v != 0);
        int pre = __popc(m & ((1u << lane) - 1u));
        if (v && (base + pre) < nseg) st[base + pre] = i;
        base += __popc(m);
    }
    __syncwarp();
    if (lane == 0) st[nseg] = L;
}

// ---------------- segment mean pooling -----------------------------------
__global__ void pool_kernel(const float* __restrict__ x, float* __restrict__ out,
                            const int* __restrict__ starts, int Lin, int nseg) {
    int b = blockIdx.y, s = blockIdx.x;
    const int* st = starts + (long)b * (nseg + 1);
    int beg = st[s], end = st[s + 1];
    int t = threadIdx.x;             // 128
    float4 acc = make_float4(0.f, 0.f, 0.f, 0.f);
    for (int r = beg; r < end; r++) {
        float4 v = ((const float4*)(x + ((long)b * Lin + r) * Dm))[t];
        acc.x += v.x; acc.y += v.y; acc.z += v.z; acc.w += v.w;
    }
    int c = end - beg; if (c < 1) c = 1;
    float inv = 1.0f / (float)c;
    acc.x *= inv; acc.y *= inv; acc.z *= inv; acc.w *= inv;
    ((float4*)(out + ((long)b * nseg + s) * Dm))[t] = acc;
}

// ---------------- layernorm (row per block, D=512) ------------------------
__global__ void ln_kernel(const float* __restrict__ x, float* __restrict__ y,
                          const float* __restrict__ g, const float* __restrict__ bt) {
    long row = blockIdx.x;
    int t = threadIdx.x;             // 128
    float4 v = ((const float4*)(x + row * Dm))[t];
    float s  = v.x + v.y + v.z + v.w;
    float sq = v.x * v.x + v.y * v.y + v.z * v.z + v.w * v.w;
    __shared__ float sh[8];
    __shared__ float stats[2];
    for (int o = 16; o; o >>= 1) {
        s  += __shfl_xor_sync(0xffffffffu, s, o);
        sq += __shfl_xor_sync(0xffffffffu, sq, o);
    }
    int w = t >> 5;
    if ((t & 31) == 0) { sh[w] = s; sh[4 + w] = sq; }
    __syncthreads();
    if (t == 0) {
        float S = sh[0] + sh[1] + sh[2] + sh[3];
        float Q = sh[4] + sh[5] + sh[6] + sh[7];
        float mu = S * (1.0f / 512.0f);
        float var = Q * (1.0f / 512.0f) - mu * mu;
        stats[0] = mu; stats[1] = rsqrtf(var + 1e-5f);
    }
    __syncthreads();
    float mu = stats[0], inv = stats[1];
    float4 gg = ((const float4*)g)[t];
    float4 bb = ((const float4*)bt)[t];
    float4 o;
    o.x = (v.x - mu) * inv * gg.x + bb.x;
    o.y = (v.y - mu) * inv * gg.y + bb.y;
    o.z = (v.z - mu) * inv * gg.z + bb.z;
    o.w = (v.w - mu) * inv * gg.w + bb.w;
    ((float4*)(y + row * Dm))[t] = o;
}

// ---------------- row softmax ---------------------------------------------
__global__ void softmax_kernel(float* __restrict__ sc, int L) {
    long row = blockIdx.x;
    float* r = sc + row * (long)L;
    int t = threadIdx.x;             // 128
    __shared__ float wr[4];
    __shared__ float bval;
    float mx = -3.4e38f;
    for (int i = t; i < L; i += 128) mx = fmaxf(mx, r[i]);
    for (int o = 16; o; o >>= 1) mx = fmaxf(mx, __shfl_xor_sync(0xffffffffu, mx, o));
    if ((t & 31) == 0) wr[t >> 5] = mx;
    __syncthreads();
    if (t == 0) bval = fmaxf(fmaxf(wr[0], wr[1]), fmaxf(wr[2], wr[3]));
    __syncthreads();
    mx = bval;
    __syncthreads();
    float s = 0.f;
    for (int i = t; i < L; i += 128) { float e = expf(r[i] - mx); r[i] = e; s += e; }
    for (int o = 16; o; o >>= 1) s += __shfl_xor_sync(0xffffffffu, s, o);
    if ((t & 31) == 0) wr[t >> 5] = s;
    __syncthreads();
    if (t == 0) bval = wr[0] + wr[1] + wr[2] + wr[3];
    __syncthreads();
    float inv = 1.0f / bval;
    for (int i = t; i < L; i += 128) r[i] *= inv;
}

// ---------------- generic 64x64x16 SGEMM, strided batch over (b,h) --------
// C = alpha * A(MxK) * op(B)(KxN) [+ bias[n]] [gelu] [+ res] ; all dims %64/%16
#define TS 64
#define KS 16
__global__ void __launch_bounds__(256) gemm64(
    const float* __restrict__ A, const float* __restrict__ Bm,
    const float* __restrict__ bias, const float* __restrict__ res,
    float* __restrict__ C,
    int M, int N, int K, int lda, int ldb, int ldc, int ldres,
    long sAb, long sAh, long sBb, long sBh, long sCb, long sCh, long sRb,
    int nH, float alpha, int transB, int doGelu)
{
    int z = blockIdx.z;
    int bb = z / nH, hh = z - bb * nH;
    A  += bb * sAb + hh * sAh;
    Bm += bb * sBb + hh * sBh;
    C  += bb * sCb + hh * sCh;
    if (res) res += bb * sRb;

    __shared__ float As[KS][TS + 1];
    __shared__ float Bs[KS][TS + 1];
    int tid = threadIdx.x;
    int tx = tid & 15, ty = tid >> 4;      // 16x16 threads
    int m0 = blockIdx.y * TS, n0 = blockIdx.x * TS;
    float acc[4][4] = {};

    for (int k0 = 0; k0 < K; k0 += KS) {
        #pragma unroll
        for (int i = 0; i < 4; i++) {
            int lin = tid + i * 256;
            int kk = lin & 15, m = lin >> 4;
            As[kk][m] = A[(long)(m0 + m) * lda + (k0 + kk)];
        }
        if (!transB) {
            #pragma unroll
            for (int i = 0; i < 4; i++) {
                int lin = tid + i * 256;
                int n = lin & 63, kk = lin >> 6;
                Bs[kk][n] = Bm[(long)(k0 + kk) * ldb + (n0 + n)];
            }
        } else {
            #pragma unroll
            for (int i = 0; i < 4; i++) {
                int lin = tid + i * 256;
                int kk = lin & 15, n = lin >> 4;
                Bs[kk][n] = Bm[(long)(n0 + n) * ldb + (k0 + kk)];
            }
        }
        __syncthreads();
        #pragma unroll
        for (int kk = 0; kk < KS; kk++) {
            float a[4], b[4];
            #pragma unroll
            for (int i = 0; i < 4; i++) a[i] = As[kk][ty * 4 + i];
            #pragma unroll
            for (int j = 0; j < 4; j++) b[j] = Bs[kk][tx * 4 + j];
            #pragma unroll
            for (int i = 0; i < 4; i++)
                #pragma unroll
                for (int j = 0; j < 4; j++)
                    acc[i][j] = fmaf(a[i], b[j], acc[i][j]);
        }
        __syncthreads();
    }
    #pragma unroll
    for (int i = 0; i < 4; i++) {
        int m = m0 + ty * 4 + i;
        #pragma unroll
        for (int j = 0; j < 4; j++) {
            int n = n0 + tx * 4 + j;
            float c = alpha * acc[i][j];
            if (bias) c += bias[n];
            if (doGelu) c = 0.5f * c * (1.0f + erff(c * 0.70710678118654752f));
            if (res) c += res[(long)m * ldres + n];
            C[(long)m * ldc + n] = c;
        }
    }
}

// ---------------- host-side helpers --------------------------------------
static inline void gemm_simple(const float* A, const float* B, const float* bias,
                               const float* res, float* C,
                               int M, int N, int K, int gelu) {
    dim3 g(N / 64, M / 64, 1);
    gemm64<<<g, 256>>>(A, B, bias, res, C, M, N, K, K, N, N, N,
                       0, 0, 0, 0, 0, 0, 0, 1, 1.0f, 0, gelu);
}

// projections: A [M,512] lda=512, W [512,512] row-major, C [M,512]
static inline void proj(const float* A, const float* W, const float* b,
                        const float* res, float* C, int M) {
    dim3 g(512 / 64, M / 64, 1);
    gemm64<<<g, 256>>>(A, W, b, res, C, M, 512, 512, 512, 512, 512, 512,
                       0, 0, 0, 0, 0, 0, 0, 1, 1.0f, 0, 0);
}

static void run_mlp(float* P, int M, int l,
                    const float* lng, const float* lnb,
                    const float* w1, const float* b1,
                    const float* w2, const float* b2,
                    float* lnbuf, float* hbuf) {
    ln_kernel<<<M, 128>>>(P, lnbuf, lng + l * 512, lnb + l * 512);
    // h = gelu(ln @ W1 + b1) : [M,1024]
    {
        dim3 g(1024 / 64, M / 64, 1);
        gemm64<<<g, 256>>>(lnbuf, w1 + (long)l * 512 * 1024, b1 + l * 1024, nullptr,
                           hbuf, M, 1024, 512, 512, 1024, 1024, 0,
                           0, 0, 0, 0, 0, 0, 0, 1, 1.0f, 0, 1);
    }
    // P = P + h @ W2 + b2
    {
        dim3 g(512 / 64, M / 64, 1);
        gemm64<<<g, 256>>>(hbuf, w2 + (long)l * 1024 * 512, b2 + l * 512, P,
                           P, M, 512, 1024, 1024, 512, 512, 512,
                           0, 0, 0, 0, 0, 0, 0, 1, 1.0f, 0, 0);
    }
}

// one-direction MHA: q-side input xq (already LN'd), kv-side xkv
static void mha(const float* xq_ln, int Sq, const float* xkv, int Skv,
                const float* W, const float* Bv,  // 4 weights/biases starting here
                const float* resid, float* out,
                float* qb, float* kb, float* vb, float* aob, float* scb) {
    int Mq = 4 * Sq, Mkv = 4 * Skv;
    proj(xq_ln, W + 0 * DD, Bv + 0 * 512, nullptr, qb, Mq);
    proj(xkv,   W + 1 * DD, Bv + 1 * 512, nullptr, kb, Mkv);
    proj(xkv,   W + 2 * DD, Bv + 2 * 512, nullptr, vb, Mkv);
    // scores[b,h,q,k] = alpha * Q Kt  (M=Sq, N=Skv, K=128) over 16 (b,h)
    {
        dim3 g(Skv / 64, Sq / 64, 16);
        gemm64<<<g, 256>>>(qb, kb, nullptr, nullptr, scb,
                           Sq, Skv, 128, 512, 512, Skv, 0,
                           (long)Sq * 512, 128, (long)Skv * 512, 128,
                           (long)4 * Sq * Skv, (long)Sq * Skv, 0,
                           4, 0.08838834764831845f, 1, 0);
    }
    softmax_kernel<<<16 * Sq, 128>>>(scb, Skv);
    // AO[b,q,h*128..] = P V   (M=Sq, N=128, K=Skv)
    {
        dim3 g(128 / 64, Sq / 64, 16);
        gemm64<<<g, 256>>>(scb, vb, nullptr, nullptr, aob,
                           Sq, 128, Skv, Skv, 512, 512, 0,
                           (long)4 * Sq * Skv, (long)Sq * Skv,
                           (long)Skv * 512, 128, (long)Sq * 512, 128, 0,
                           4, 1.0f, 0, 0);
    }
    // out = resid + AO @ Wo + bo
    proj(aob, W + 3 * DD, Bv + 3 * 512, resid, out, Mq);
}

extern "C" void kernel_launch(void* const* d_in, const int* in_sizes, int n_in,
                              void* d_out, int out_size) {
    const float* h_bytes   = (const float*)d_in[0];
    const int*   b0        = (const int*)d_in[1];
    const int*   b1        = (const int*)d_in[2];
    const int*   b2        = (const int*)d_in[3];
    const float* mlp_ln_g  = (const float*)d_in[4];
    const float* mlp_ln_b  = (const float*)d_in[5];
    const float* mlp_w1    = (const float*)d_in[6];
    const float* mlp_b1    = (const float*)d_in[7];
    const float* mlp_w2    = (const float*)d_in[8];
    const float* mlp_b2    = (const float*)d_in[9];
    const float* ca_w      = (const float*)d_in[10];
    const float* ca_b      = (const float*)d_in[11];
    const float* ca_ln_g   = (const float*)d_in[12];
    const float* ca_ln_b   = (const float*)d_in[13];

    float *seg0, *seg1, *seg2, *lnbuf, *hbuf, *qb, *kb, *vb, *aob, *scb;
    int* st;
    cudaGetSymbolAddress((void**)&seg0, g_seg0);
    cudaGetSymbolAddress((void**)&seg1, g_seg1);
    cudaGetSymbolAddress((void**)&seg2, g_seg2);
    cudaGetSymbolAddress((void**)&lnbuf, g_ln);
    cudaGetSymbolAddress((void**)&hbuf, g_h);
    cudaGetSymbolAddress((void**)&qb, g_q);
    cudaGetSymbolAddress((void**)&kb, g_k);
    cudaGetSymbolAddress((void**)&vb, g_v);
    cudaGetSymbolAddress((void**)&aob, g_ao);
    cudaGetSymbolAddress((void**)&scb, g_sc);
    cudaGetSymbolAddress((void**)&st, g_starts);

    int* st0 = st;
    int* st1 = st + 4 * 1025;
    int* st2 = st1 + 4 * 257;

    float* OUT0 = (float*)d_out;                      // segs[0] [4,1024,512]
    float* OUT1 = OUT0 + (long)4 * 1024 * 512;        // segs[1] [4,256,512]
    float* OUT2 = OUT1 + (long)4 * 256 * 512;         // segs[2] [4,64,512]

    // ---- boundary scans ----
    starts_kernel<<<4, 32>>>(b0, st0, 8192, 1024);
    starts_kernel<<<4, 32>>>(b1, st1, 1024, 256);
    starts_kernel<<<4, 32>>>(b2, st2, 256, 64);

    // ---- pooling + per-level MLP ----
    pool_kernel<<<dim3(1024, 4), 128>>>(h_bytes, seg0, st0, 8192, 1024);
    run_mlp(seg0, 4096, 0, mlp_ln_g, mlp_ln_b, mlp_w1, mlp_b1, mlp_w2, mlp_b2, lnbuf, hbuf);
    pool_kernel<<<dim3(256, 4), 128>>>(seg0, seg1, st1, 1024, 256);
    run_mlp(seg1, 1024, 1, mlp_ln_g, mlp_ln_b, mlp_w1, mlp_b1, mlp_w2, mlp_b2, lnbuf, hbuf);
    pool_kernel<<<dim3(64, 4), 128>>>(seg1, seg2, st2, 256, 64);
    run_mlp(seg2, 256, 2, mlp_ln_g, mlp_ln_b, mlp_w1, mlp_b1, mlp_w2, mlp_b2, lnbuf, hbuf);

    // ---- cross-level block i=1 : fine=seg1 (Sf=256), coarse=seg2 (Sc=64) ----
    {
        const float* W  = ca_w + (long)1 * 8 * DD;
        const float* Bv = ca_b + (long)1 * 8 * 512;
        const float* lg = ca_ln_g + (long)1 * 2 * 512;
        const float* lb = ca_ln_b + (long)1 * 2 * 512;
        // bu: fu = fine + MHA(LN(fine), coarse)   -> seg1 (in place)
        ln_kernel<<<4 * 256, 128>>>(seg1, lnbuf, lg, lb);
        mha(lnbuf, 256, seg2, 64, W, Bv, seg1, seg1, qb, kb, vb, aob, scb);
        // td: cu = coarse + MHA(LN(coarse), fu)   -> OUT2 (final segs[2])
        ln_kernel<<<4 * 64, 128>>>(seg2, lnbuf, lg + 512, lb + 512);
        mha(lnbuf, 64, seg1, 256, W + 4 * DD, Bv + 4 * 512, seg2, OUT2,
            qb, kb, vb, aob, scb);
    }

    // ---- cross-level block i=0 : fine=seg0 (Sf=1024), coarse=seg1 (Sc=256) ----
    {
        const float* W  = ca_w;
        const float* Bv = ca_b;
        const float* lg = ca_ln_g;
        const float* lb = ca_ln_b;
        // bu: fu -> OUT0 (final segs[0])
        ln_kernel<<<4 * 1024, 128>>>(seg0, lnbuf, lg, lb);
        mha(lnbuf, 1024, seg1, 256, W, Bv, seg0, OUT0, qb, kb, vb, aob, scb);
        // td: cu -> OUT1 (final segs[1]); kv = fu (OUT0)
        ln_kernel<<<4 * 256, 128>>>(seg1, lnbuf, lg + 512, lb + 512);
        mha(lnbuf, 256, OUT0, 1024, W + 4 * DD, Bv + 4 * 512, seg1, OUT1,
            qb, kb, vb, aob, scb);
    }
}